// round 1
// baseline (speedup 1.0000x reference)
#include <cuda_runtime.h>

#define HH 256
#define WW 256
#define C 64
#define O 64
#define B 16
#define NK 4
#define TILE 16
#define GROUPS 8

// ---- scratch (no allocations allowed) ----
__device__ float g_w[B * O * C * 9];        // per-batch demodulated weights
__device__ float g_sum[B * GROUPS];         // groupnorm sum
__device__ float g_sumsq[B * GROUPS];       // groupnorm sum of squares

// ============================================================================
// Kernel 0: softmax kernel selection + modulation + demodulation.
// grid (O, B), 64 threads (one per input channel i). Also zeros GN stats.
// ============================================================================
__global__ void weight_kernel(const float* __restrict__ mod,
                              const float* __restrict__ kmod,
                              const float* __restrict__ cw) {
    int o = blockIdx.x;
    int b = blockIdx.y;
    int i = threadIdx.x;  // 0..63

    // softmax over 4 kernel logits (redundant per thread, trivial cost)
    float k0 = kmod[b * NK + 0], k1 = kmod[b * NK + 1];
    float k2 = kmod[b * NK + 2], k3 = kmod[b * NK + 3];
    float m = fmaxf(fmaxf(k0, k1), fmaxf(k2, k3));
    float e0 = __expf(k0 - m), e1 = __expf(k1 - m);
    float e2 = __expf(k2 - m), e3 = __expf(k3 - m);
    float inv = 1.0f / (e0 + e1 + e2 + e3);
    float a0 = e0 * inv, a1 = e1 * inv, a2 = e2 * inv, a3 = e3 * inv;

    float mi = mod[b * C + i] + 1.0f;

    float wv[9];
    float ss = 0.0f;
#pragma unroll
    for (int k = 0; k < 9; k++) {
        int base = (o * C + i) * 9 + k;
        const int stride = O * C * 9;
        float v = a0 * cw[base] + a1 * cw[stride + base] +
                  a2 * cw[2 * stride + base] + a3 * cw[3 * stride + base];
        v *= mi;
        wv[k] = v;
        ss += v * v;
    }
    // block reduce ss over 64 threads
#pragma unroll
    for (int off = 16; off; off >>= 1)
        ss += __shfl_xor_sync(0xffffffffu, ss, off);
    __shared__ float sh[2];
    if ((i & 31) == 0) sh[i >> 5] = ss;
    __syncthreads();
    float tot = sh[0] + sh[1];
    float innorm = rsqrtf(fmaxf(tot, 1e-8f));  // clip(ss, EPS_DEMOD) then rsqrt

#pragma unroll
    for (int k = 0; k < 9; k++)
        g_w[((b * O + o) * C + i) * 9 + k] = wv[k] * innorm;

    // zero GN accumulators each launch (graph replays re-run this first)
    if (o == 0 && i < GROUPS) {
        g_sum[b * GROUPS + i] = 0.0f;
        g_sumsq[b * GROUPS + i] = 0.0f;
    }
}

// ============================================================================
// Kernel 1: per-sample 3x3 conv (SAME) + GN partial statistics.
// grid (16, 16, B): one CTA per 16x16 spatial tile of one batch element.
// 256 threads; thread = 8 consecutive px (one row half) x 8 out-channels.
// All 8 out-channels of a thread fall in one GN group -> cheap stats reduce.
// Dynamic smem: x halo tile [64][18][18] fp32 = 82944 B.
// ============================================================================
__global__ void __launch_bounds__(256, 2)
conv_kernel(const float* __restrict__ x, float* __restrict__ y) {
    extern __shared__ float xs[];  // [C][18][18]
    __shared__ float gsum[GROUPS], gsq[GROUPS];

    int b = blockIdx.z;
    int h0 = blockIdx.y * TILE;
    int w0 = blockIdx.x * TILE;
    int tid = threadIdx.x;

    if (tid < GROUPS) { gsum[tid] = 0.0f; gsq[tid] = 0.0f; }

    // ---- stage x tile with halo (zero padded) ----
    const float* xb = x + (long long)b * C * HH * WW;
    for (int idx = tid; idx < C * 18 * 18; idx += 256) {
        int ci = idx / 324;
        int rem = idx - ci * 324;
        int rr = rem / 18;
        int cc = rem - rr * 18;
        int gh = h0 + rr - 1;
        int gw = w0 + cc - 1;
        float v = 0.0f;
        if ((unsigned)gh < HH && (unsigned)gw < WW)
            v = xb[ci * (HH * WW) + gh * WW + gw];
        xs[idx] = v;
    }
    __syncthreads();

    int cg = tid & 7;          // out-channel group (== GN group index)
    int pg = tid >> 3;         // 0..31 pixel-strip id
    int r  = pg >> 1;          // output row within tile 0..15
    int c0 = (pg & 1) * 8;     // output col base within tile (0 or 8)

    float acc[8][8];           // [px][co_local]
#pragma unroll
    for (int p = 0; p < 8; p++)
#pragma unroll
        for (int q = 0; q < 8; q++) acc[p][q] = 0.0f;

    const float* wb = g_w + (long long)b * O * C * 9;

    for (int ci = 0; ci < C; ci++) {
        // x window for this thread's strip: rows r..r+2 (halo coords), cols c0..c0+9
        float xv[3][10];
#pragma unroll
        for (int tr = 0; tr < 3; tr++) {
            const float* sp = &xs[ci * 324 + (r + tr) * 18 + c0];
#pragma unroll
            for (int k = 0; k < 10; k++) xv[tr][k] = sp[k];
        }
#pragma unroll
        for (int col = 0; col < 8; col++) {
            const float* wp = wb + ((cg * 8 + col) * C + ci) * 9;
            float w0_ = wp[0], w1_ = wp[1], w2_ = wp[2];
            float w3_ = wp[3], w4_ = wp[4], w5_ = wp[5];
            float w6_ = wp[6], w7_ = wp[7], w8_ = wp[8];
#pragma unroll
            for (int px = 0; px < 8; px++) {
                float s = acc[px][col];
                s = fmaf(w0_, xv[0][px],     s);
                s = fmaf(w1_, xv[0][px + 1], s);
                s = fmaf(w2_, xv[0][px + 2], s);
                s = fmaf(w3_, xv[1][px],     s);
                s = fmaf(w4_, xv[1][px + 1], s);
                s = fmaf(w5_, xv[1][px + 2], s);
                s = fmaf(w6_, xv[2][px],     s);
                s = fmaf(w7_, xv[2][px + 1], s);
                s = fmaf(w8_, xv[2][px + 2], s);
                acc[px][col] = s;
            }
        }
    }

    // ---- store conv output (pre-norm) + local GN stats ----
    float s = 0.0f, s2 = 0.0f;
    float* yb = y + (long long)b * O * HH * WW;
    int gh = h0 + r;
    int gw = w0 + c0;
#pragma unroll
    for (int col = 0; col < 8; col++) {
        int co = cg * 8 + col;
        float4 v0 = make_float4(acc[0][col], acc[1][col], acc[2][col], acc[3][col]);
        float4 v1 = make_float4(acc[4][col], acc[5][col], acc[6][col], acc[7][col]);
        float* dst = yb + co * (HH * WW) + gh * WW + gw;
        *(float4*)dst = v0;
        *(float4*)(dst + 4) = v1;
#pragma unroll
        for (int px = 0; px < 8; px++) {
            float v = acc[px][col];
            s += v;
            s2 += v * v;
        }
    }

    // reduce over lanes sharing the same cg (lanes l, l+8, l+16, l+24)
#pragma unroll
    for (int off = 8; off < 32; off <<= 1) {
        s  += __shfl_xor_sync(0xffffffffu, s, off);
        s2 += __shfl_xor_sync(0xffffffffu, s2, off);
    }
    if ((tid & 31) < 8) {
        atomicAdd(&gsum[cg], s);
        atomicAdd(&gsq[cg], s2);
    }
    __syncthreads();
    if (tid < GROUPS) {
        atomicAdd(&g_sum[b * GROUPS + tid], gsum[tid]);
        atomicAdd(&g_sumsq[b * GROUPS + tid], gsq[tid]);
    }
}

// ============================================================================
// Kernel 2: GroupNorm finalize + SiLU, in-place on d_out, float4 vectorized.
// ============================================================================
__global__ void norm_kernel(float* __restrict__ y,
                            const float* __restrict__ gamma,
                            const float* __restrict__ beta) {
    long long i = (long long)blockIdx.x * blockDim.x + threadIdx.x;
    long long base = i * 4;
    int cidx = (int)(base >> 16);    // plane = b*64 + c (65536 floats per plane)
    int b = cidx >> 6;
    int c = cidx & 63;
    int g = c >> 3;

    const float invN = 1.0f / (8.0f * HH * WW);
    float mean = g_sum[b * GROUPS + g] * invN;
    float var = g_sumsq[b * GROUPS + g] * invN - mean * mean;
    float istd = rsqrtf(var + 1e-5f);
    float ga = gamma[c], be = beta[c];

    float4 v = *(float4*)&y[base];
    float* vp = &v.x;
#pragma unroll
    for (int k = 0; k < 4; k++) {
        float t = (vp[k] - mean) * istd * ga + be;
        vp[k] = t / (1.0f + __expf(-t));   // SiLU
    }
    *(float4*)&y[base] = v;
}

// ============================================================================
extern "C" void kernel_launch(void* const* d_in, const int* in_sizes, int n_in,
                              void* d_out, int out_size) {
    const float* x     = (const float*)d_in[0];
    const float* mod   = (const float*)d_in[1];
    const float* kmod  = (const float*)d_in[2];
    const float* cw    = (const float*)d_in[3];
    const float* gamma = (const float*)d_in[4];
    const float* beta  = (const float*)d_in[5];
    float* out = (float*)d_out;

    const int smem = C * 18 * 18 * (int)sizeof(float);  // 82944 B
    cudaFuncSetAttribute(conv_kernel,
                         cudaFuncAttributeMaxDynamicSharedMemorySize, smem);

    weight_kernel<<<dim3(O, B), 64>>>(mod, kmod, cw);
    conv_kernel<<<dim3(16, 16, B), 256, smem>>>(x, out);
    norm_kernel<<<(B * O * HH * WW / 4) / 256, 256>>>(out, gamma, beta);
}